// round 1
// baseline (speedup 1.0000x reference)
#include <cuda_runtime.h>
#include <cstddef>

#define AN 8192          // sequence length
#define AC 256           // channels
#define AH 4             // heads
#define AD 64            // head dim
#define AC2 512          // 2*C

// ---------------- scratch (allocation-free, device globals) ----------------
__device__ float g_XM[(size_t)AC2 * AN];      // rows 0..255: X = descs^T ; rows 256..511: Wm@msg
__device__ float g_Q[(size_t)AH * AN * AD];   // [h][n][d]
__device__ float g_K[(size_t)AH * AN * AD];
__device__ float g_V[(size_t)AH * AN * AD];
__device__ float g_Msg[(size_t)AC * AN];      // attention output, channel-major [c][n]
__device__ float g_Y[(size_t)AC2 * AN];       // after W1 (then normed in place)
__device__ float g_Z[(size_t)AC * AN];        // after W2

// ---------------- transpose: X[c][n] = descs[n][c] ----------------
__global__ __launch_bounds__(256) void transpose_in(const float* __restrict__ descs,
                                                    float* __restrict__ X) {
    __shared__ float tile[32][33];
    int n0 = blockIdx.x * 32, c0 = blockIdx.y * 32;
    int tx = threadIdx.x, ty = threadIdx.y;
#pragma unroll
    for (int r = 0; r < 4; r++) {
        int n = n0 + ty + r * 8;
        tile[ty + r * 8][tx] = descs[(size_t)n * AC + c0 + tx];
    }
    __syncthreads();
#pragma unroll
    for (int r = 0; r < 4; r++) {
        int c = c0 + ty + r * 8;
        X[(size_t)c * AN + n0 + tx] = tile[tx][ty + r * 8];
    }
}

// ---------------- out[n][c] = descs[n][c] + Z[c][n] ----------------
__global__ __launch_bounds__(256) void transpose_add(const float* __restrict__ descs,
                                                     const float* __restrict__ Z,
                                                     float* __restrict__ out) {
    __shared__ float tile[32][33];
    int n0 = blockIdx.x * 32, c0 = blockIdx.y * 32;
    int tx = threadIdx.x, ty = threadIdx.y;
#pragma unroll
    for (int r = 0; r < 4; r++) {
        int c = c0 + ty + r * 8;
        tile[ty + r * 8][tx] = Z[(size_t)c * AN + n0 + tx];
    }
    __syncthreads();
#pragma unroll
    for (int r = 0; r < 4; r++) {
        int n = n0 + ty + r * 8;
        size_t idx = (size_t)n * AC + c0 + tx;
        out[idx] = descs[idx] + tile[tx][ty + r * 8];
    }
}

// ---------------- generic fp32 GEMM: C = A[M,K] @ B[K,N] + bias ----------------
// OUTMODE 0: C[m][n] row-major.  OUTMODE 1: QKV permute -> out[(m%4)][n][(m/4)]
template <int OUTMODE>
__global__ __launch_bounds__(256) void gemm_k(const float* __restrict__ A,
                                              const float* __restrict__ B,
                                              const float* __restrict__ bias,
                                              float* __restrict__ C,
                                              int M, int Nn, int K) {
    __shared__ float As[16][64];   // As[k][m]
    __shared__ float Bs[16][64];   // Bs[k][n]
    int tid = threadIdx.x;
    int n0 = blockIdx.x * 64;
    int m0 = blockIdx.y * 64;
    int tx = tid & 15, ty = tid >> 4;
    int ar = tid >> 2, ac4 = tid & 3;   // A loader: row (0..63), float4 col (0..3)
    int br = tid >> 4, bc4 = tid & 15;  // B loader: row (0..15), float4 col (0..15)

    float acc[4][4];
#pragma unroll
    for (int i = 0; i < 4; i++)
#pragma unroll
        for (int j = 0; j < 4; j++) acc[i][j] = 0.f;

    for (int k0 = 0; k0 < K; k0 += 16) {
        float4 a = *(const float4*)&A[(size_t)(m0 + ar) * K + k0 + ac4 * 4];
        float4 b = *(const float4*)&B[(size_t)(k0 + br) * Nn + n0 + bc4 * 4];
        __syncthreads();
        As[ac4 * 4 + 0][ar] = a.x;
        As[ac4 * 4 + 1][ar] = a.y;
        As[ac4 * 4 + 2][ar] = a.z;
        As[ac4 * 4 + 3][ar] = a.w;
        *(float4*)&Bs[br][bc4 * 4] = b;
        __syncthreads();
#pragma unroll
        for (int kk = 0; kk < 16; kk++) {
            float4 av = *(const float4*)&As[kk][ty * 4];
            float4 bv = *(const float4*)&Bs[kk][tx * 4];
            float ra[4] = {av.x, av.y, av.z, av.w};
            float rb[4] = {bv.x, bv.y, bv.z, bv.w};
#pragma unroll
            for (int i = 0; i < 4; i++)
#pragma unroll
                for (int j = 0; j < 4; j++) acc[i][j] = fmaf(ra[i], rb[j], acc[i][j]);
        }
    }
#pragma unroll
    for (int i = 0; i < 4; i++) {
        int m = m0 + ty * 4 + i;
        float bv = bias[m];
#pragma unroll
        for (int j = 0; j < 4; j++) {
            int n = n0 + tx * 4 + j;
            float val = acc[i][j] + bv;
            if (OUTMODE == 0) {
                C[(size_t)m * Nn + n] = val;
            } else {
                // channel m = d*4 + h -> [h][n][d]
                C[(size_t)(m & 3) * ((size_t)Nn * AD) + (size_t)n * AD + (m >> 2)] = val;
            }
        }
    }
}

// ---------------- flash attention (fp32, online softmax) ----------------
// grid: (AN/256, AH), 256 threads, 1 query per thread
__global__ __launch_bounds__(256) void attn_k(const float* __restrict__ Qp,
                                              const float* __restrict__ Kp,
                                              const float* __restrict__ Vp,
                                              float* __restrict__ Msg) {
    __shared__ float4 ksh[64 * 16];
    __shared__ float4 vsh[64 * 16];
    int h = blockIdx.y;
    int n = blockIdx.x * 256 + threadIdx.x;

    const float4* qrow = (const float4*)(Qp + ((size_t)h * AN + n) * AD);
    float4 q4[16];
#pragma unroll
    for (int i = 0; i < 16; i++) {
        float4 t = qrow[i];
        t.x *= 0.125f; t.y *= 0.125f; t.z *= 0.125f; t.w *= 0.125f;  // 1/sqrt(64)
        q4[i] = t;
    }
    float4 O4[16];
#pragma unroll
    for (int i = 0; i < 16; i++) O4[i] = make_float4(0.f, 0.f, 0.f, 0.f);
    float mx = -1e30f, l = 0.f;

    for (int m0 = 0; m0 < AN; m0 += 64) {
        const float4* Ks = (const float4*)(Kp + ((size_t)h * AN + m0) * AD);
        const float4* Vs = (const float4*)(Vp + ((size_t)h * AN + m0) * AD);
        __syncthreads();
#pragma unroll
        for (int i = 0; i < 4; i++) {
            int idx = threadIdx.x + i * 256;
            ksh[idx] = Ks[idx];
            vsh[idx] = Vs[idx];
        }
        __syncthreads();
#pragma unroll 2
        for (int j = 0; j < 64; j++) {
            const float4* kr = &ksh[j * 16];
            float s0 = 0.f, s1 = 0.f, s2 = 0.f, s3 = 0.f;
#pragma unroll
            for (int i = 0; i < 16; i += 4) {
                float4 t0 = kr[i + 0], t1 = kr[i + 1], t2 = kr[i + 2], t3 = kr[i + 3];
                s0 = fmaf(q4[i + 0].w, t0.w, fmaf(q4[i + 0].z, t0.z, fmaf(q4[i + 0].y, t0.y, fmaf(q4[i + 0].x, t0.x, s0))));
                s1 = fmaf(q4[i + 1].w, t1.w, fmaf(q4[i + 1].z, t1.z, fmaf(q4[i + 1].y, t1.y, fmaf(q4[i + 1].x, t1.x, s1))));
                s2 = fmaf(q4[i + 2].w, t2.w, fmaf(q4[i + 2].z, t2.z, fmaf(q4[i + 2].y, t2.y, fmaf(q4[i + 2].x, t2.x, s2))));
                s3 = fmaf(q4[i + 3].w, t3.w, fmaf(q4[i + 3].z, t3.z, fmaf(q4[i + 3].y, t3.y, fmaf(q4[i + 3].x, t3.x, s3))));
            }
            float s = (s0 + s1) + (s2 + s3);
            float p;
            if (s > mx) {
                float sc = __expf(mx - s);
                l *= sc;
                mx = s;
                p = 1.f;
#pragma unroll
                for (int i = 0; i < 16; i++) {
                    O4[i].x *= sc; O4[i].y *= sc; O4[i].z *= sc; O4[i].w *= sc;
                }
            } else {
                p = __expf(s - mx);
            }
            l += p;
            const float4* vr = &vsh[j * 16];
#pragma unroll
            for (int i = 0; i < 16; i++) {
                float4 t = vr[i];
                O4[i].x = fmaf(p, t.x, O4[i].x);
                O4[i].y = fmaf(p, t.y, O4[i].y);
                O4[i].z = fmaf(p, t.z, O4[i].z);
                O4[i].w = fmaf(p, t.w, O4[i].w);
            }
        }
    }
    float inv = 1.f / l;
    // Msg[(d*4+h)*AN + n] ; base offset h*AN + n, stride d*4*AN
    float* base = Msg + (size_t)h * AN + n;
#pragma unroll
    for (int i = 0; i < 16; i++) {
        base[(size_t)(4 * i + 0) * 4 * AN] = O4[i].x * inv;
        base[(size_t)(4 * i + 1) * 4 * AN] = O4[i].y * inv;
        base[(size_t)(4 * i + 2) * 4 * AN] = O4[i].z * inv;
        base[(size_t)(4 * i + 3) * 4 * AN] = O4[i].w * inv;
    }
}

// ---------------- InstanceNorm (biased var) + ReLU, in place, per channel ----------------
__global__ __launch_bounds__(256) void inorm_relu(float* __restrict__ Y) {
    const int Nn = AN;
    float* row = Y + (size_t)blockIdx.x * Nn;
    __shared__ float red[256];
    int tid = threadIdx.x;

    float s = 0.f;
    for (int i = tid; i < Nn; i += 256) s += row[i];
    red[tid] = s;
    __syncthreads();
    for (int off = 128; off > 0; off >>= 1) {
        if (tid < off) red[tid] += red[tid + off];
        __syncthreads();
    }
    float mean = red[0] * (1.f / Nn);
    __syncthreads();

    float ss = 0.f;
    for (int i = tid; i < Nn; i += 256) {
        float d = row[i] - mean;
        ss += d * d;
    }
    red[tid] = ss;
    __syncthreads();
    for (int off = 128; off > 0; off >>= 1) {
        if (tid < off) red[tid] += red[tid + off];
        __syncthreads();
    }
    float rstd = rsqrtf(red[0] * (1.f / Nn) + 1e-5f);

    for (int i = tid; i < Nn; i += 256) {
        float v = (row[i] - mean) * rstd;
        row[i] = v > 0.f ? v : 0.f;
    }
}

// ---------------- launch ----------------
extern "C" void kernel_launch(void* const* d_in, const int* in_sizes, int n_in,
                              void* d_out, int out_size) {
    const float* descs = (const float*)d_in[0];
    const float* Wq = (const float*)d_in[1];
    const float* bq = (const float*)d_in[2];
    const float* Wk = (const float*)d_in[3];
    const float* bk = (const float*)d_in[4];
    const float* Wv = (const float*)d_in[5];
    const float* bv = (const float*)d_in[6];
    const float* Wm = (const float*)d_in[7];
    const float* bm = (const float*)d_in[8];
    const float* W1 = (const float*)d_in[9];
    const float* b1 = (const float*)d_in[10];
    const float* W2 = (const float*)d_in[11];
    const float* b2 = (const float*)d_in[12];
    float* out = (float*)d_out;

    float *xm, *q, *k, *v, *msg, *y, *z;
    cudaGetSymbolAddress((void**)&xm, g_XM);
    cudaGetSymbolAddress((void**)&q, g_Q);
    cudaGetSymbolAddress((void**)&k, g_K);
    cudaGetSymbolAddress((void**)&v, g_V);
    cudaGetSymbolAddress((void**)&msg, g_Msg);
    cudaGetSymbolAddress((void**)&y, g_Y);
    cudaGetSymbolAddress((void**)&z, g_Z);

    dim3 tb(32, 8);

    // 1) X = descs^T into g_XM rows [0,256)
    transpose_in<<<dim3(AN / 32, AC / 32), tb>>>(descs, xm);

    // 2) Q/K/V projections, written directly in [h][n][d]
    gemm_k<1><<<dim3(AN / 64, AC / 64), 256>>>(Wq, xm, bq, q, AC, AN, AC);
    gemm_k<1><<<dim3(AN / 64, AC / 64), 256>>>(Wk, xm, bk, k, AC, AN, AC);
    gemm_k<1><<<dim3(AN / 64, AC / 64), 256>>>(Wv, xm, bv, v, AC, AN, AC);

    // 3) attention -> g_Msg [c][n]
    attn_k<<<dim3(AN / 256, AH), 256>>>(q, k, v, msg);

    // 4) Wm @ msg + bm -> g_XM rows [256,512)  (forms concat(x, msg2))
    gemm_k<0><<<dim3(AN / 64, AC / 64), 256>>>(Wm, msg, bm, xm + (size_t)AC * AN, AC, AN, AC);

    // 5) Y = W1 @ concat + b1
    gemm_k<0><<<dim3(AN / 64, AC2 / 64), 256>>>(W1, xm, b1, y, AC2, AN, AC2);

    // 6) InstanceNorm + ReLU in place
    inorm_relu<<<AC2, 256>>>(y);

    // 7) Z = W2 @ Yn + b2
    gemm_k<0><<<dim3(AN / 64, AC / 64), 256>>>(W2, y, b2, z, AC, AN, AC2);

    // 8) out = descs + Z^T
    transpose_add<<<dim3(AN / 32, AC / 32), tb>>>(descs, z, out);
}

// round 2
// speedup vs baseline: 1.0653x; 1.0653x over previous
#include <cuda_runtime.h>
#include <cstddef>

#define AN 8192          // sequence length
#define AC 256           // channels
#define AH 4             // heads
#define AD 64            // head dim
#define AC2 512          // 2*C

typedef unsigned long long ull;

// ---------------- packed f32x2 helpers (sm_100a FFMA2 path) ----------------
__device__ __forceinline__ ull fma2(ull a, ull b, ull c) {
    ull d;
    asm("fma.rn.f32x2 %0, %1, %2, %3;" : "=l"(d) : "l"(a), "l"(b), "l"(c));
    return d;
}
__device__ __forceinline__ ull mul2(ull a, ull b) {
    ull d;
    asm("mul.rn.f32x2 %0, %1, %2;" : "=l"(d) : "l"(a), "l"(b));
    return d;
}
__device__ __forceinline__ ull add2(ull a, ull b) {
    ull d;
    asm("add.rn.f32x2 %0, %1, %2;" : "=l"(d) : "l"(a), "l"(b));
    return d;
}
__device__ __forceinline__ ull pack2(float x, float y) {
    ull r;
    asm("mov.b64 %0, {%1, %2};" : "=l"(r) : "f"(x), "f"(y));
    return r;
}
__device__ __forceinline__ void unpack2(ull v, float& x, float& y) {
    asm("mov.b64 {%0, %1}, %2;" : "=f"(x), "=f"(y) : "l"(v));
}

// ---------------- scratch (allocation-free, device globals) ----------------
__device__ float g_XM[(size_t)AC2 * AN];      // rows 0..255: X = descs^T ; rows 256..511: Wm@msg
__device__ float g_Q[(size_t)AH * AN * AD];   // [h][n][d]
__device__ float g_K[(size_t)AH * AN * AD];
__device__ float g_V[(size_t)AH * AN * AD];
__device__ float g_Msg[(size_t)AC * AN];      // attention output, channel-major [c][n]
__device__ float g_Y[(size_t)AC2 * AN];       // after W1 (then normed in place)
__device__ float g_Z[(size_t)AC * AN];        // after W2

// ---------------- transpose: X[c][n] = descs[n][c] ----------------
__global__ __launch_bounds__(256) void transpose_in(const float* __restrict__ descs,
                                                    float* __restrict__ X) {
    __shared__ float tile[32][33];
    int n0 = blockIdx.x * 32, c0 = blockIdx.y * 32;
    int tx = threadIdx.x, ty = threadIdx.y;
#pragma unroll
    for (int r = 0; r < 4; r++) {
        int n = n0 + ty + r * 8;
        tile[ty + r * 8][tx] = descs[(size_t)n * AC + c0 + tx];
    }
    __syncthreads();
#pragma unroll
    for (int r = 0; r < 4; r++) {
        int c = c0 + ty + r * 8;
        X[(size_t)c * AN + n0 + tx] = tile[tx][ty + r * 8];
    }
}

// ---------------- out[n][c] = descs[n][c] + Z[c][n] ----------------
__global__ __launch_bounds__(256) void transpose_add(const float* __restrict__ descs,
                                                     const float* __restrict__ Z,
                                                     float* __restrict__ out) {
    __shared__ float tile[32][33];
    int n0 = blockIdx.x * 32, c0 = blockIdx.y * 32;
    int tx = threadIdx.x, ty = threadIdx.y;
#pragma unroll
    for (int r = 0; r < 4; r++) {
        int c = c0 + ty + r * 8;
        tile[ty + r * 8][tx] = Z[(size_t)c * AN + n0 + tx];
    }
    __syncthreads();
#pragma unroll
    for (int r = 0; r < 4; r++) {
        int n = n0 + ty + r * 8;
        size_t idx = (size_t)n * AC + c0 + tx;
        out[idx] = descs[idx] + tile[tx][ty + r * 8];
    }
}

// ---------------- fp32 GEMM: C = A[M,K] @ B[K,N] + bias ----------------
// double-buffered smem + f32x2 inner product
// OUTMODE 0: C[m][n] row-major.  OUTMODE 1: QKV permute -> out[(m%4)][n][(m/4)]
template <int OUTMODE>
__global__ __launch_bounds__(256) void gemm_k(const float* __restrict__ A,
                                              const float* __restrict__ B,
                                              const float* __restrict__ bias,
                                              float* __restrict__ C,
                                              int M, int Nn, int K) {
    __shared__ __align__(16) float As[2][16][64];   // As[buf][k][m]
    __shared__ __align__(16) float Bs[2][16][64];   // Bs[buf][k][n]
    int tid = threadIdx.x;
    int n0 = blockIdx.x * 64;
    int m0 = blockIdx.y * 64;
    int tx = tid & 15, ty = tid >> 4;
    int ar = tid >> 2, ac4 = tid & 3;   // A loader: row (0..63), float4 col (0..3)
    int br = tid >> 4, bc4 = tid & 15;  // B loader: row (0..15), float4 col (0..15)

    ull acc2[4][2];
#pragma unroll
    for (int i = 0; i < 4; i++) { acc2[i][0] = 0ull; acc2[i][1] = 0ull; }

    // prologue: stage 0
    {
        float4 a = *(const float4*)&A[(size_t)(m0 + ar) * K + ac4 * 4];
        float4 b = *(const float4*)&B[(size_t)br * Nn + n0 + bc4 * 4];
        As[0][ac4 * 4 + 0][ar] = a.x;
        As[0][ac4 * 4 + 1][ar] = a.y;
        As[0][ac4 * 4 + 2][ar] = a.z;
        As[0][ac4 * 4 + 3][ar] = a.w;
        *(float4*)&Bs[0][br][bc4 * 4] = b;
    }
    __syncthreads();

    int nIter = K >> 4;
    for (int it = 0; it < nIter; it++) {
        int cur = it & 1;
        float4 an, bn;
        bool has_next = (it + 1 < nIter);
        if (has_next) {
            int k0 = (it + 1) << 4;
            an = *(const float4*)&A[(size_t)(m0 + ar) * K + k0 + ac4 * 4];
            bn = *(const float4*)&B[(size_t)(k0 + br) * Nn + n0 + bc4 * 4];
        }
#pragma unroll
        for (int kk = 0; kk < 16; kk++) {
            float4 av = *(const float4*)&As[cur][kk][ty * 4];
            ulonglong2 bb = *(const ulonglong2*)&Bs[cur][kk][tx * 4];
            ull a0 = pack2(av.x, av.x);
            ull a1 = pack2(av.y, av.y);
            ull a2 = pack2(av.z, av.z);
            ull a3 = pack2(av.w, av.w);
            acc2[0][0] = fma2(a0, bb.x, acc2[0][0]);
            acc2[0][1] = fma2(a0, bb.y, acc2[0][1]);
            acc2[1][0] = fma2(a1, bb.x, acc2[1][0]);
            acc2[1][1] = fma2(a1, bb.y, acc2[1][1]);
            acc2[2][0] = fma2(a2, bb.x, acc2[2][0]);
            acc2[2][1] = fma2(a2, bb.y, acc2[2][1]);
            acc2[3][0] = fma2(a3, bb.x, acc2[3][0]);
            acc2[3][1] = fma2(a3, bb.y, acc2[3][1]);
        }
        if (has_next) {
            int nxt = cur ^ 1;
            As[nxt][ac4 * 4 + 0][ar] = an.x;
            As[nxt][ac4 * 4 + 1][ar] = an.y;
            As[nxt][ac4 * 4 + 2][ar] = an.z;
            As[nxt][ac4 * 4 + 3][ar] = an.w;
            *(float4*)&Bs[nxt][br][bc4 * 4] = bn;
            __syncthreads();
        }
    }

#pragma unroll
    for (int i = 0; i < 4; i++) {
        int m = m0 + ty * 4 + i;
        float bv = bias[m];
        float c0, c1, c2, c3;
        unpack2(acc2[i][0], c0, c1);
        unpack2(acc2[i][1], c2, c3);
        float vals[4] = {c0 + bv, c1 + bv, c2 + bv, c3 + bv};
#pragma unroll
        for (int j = 0; j < 4; j++) {
            int n = n0 + tx * 4 + j;
            if (OUTMODE == 0) {
                C[(size_t)m * Nn + n] = vals[j];
            } else {
                // channel m = d*4 + h -> [h][n][d]
                C[(size_t)(m & 3) * ((size_t)Nn * AD) + (size_t)n * AD + (m >> 2)] = vals[j];
            }
        }
    }
}

// ---------------- flash attention (fp32, f32x2 math, online softmax) ----------------
// grid: (AN/256, AH), 256 threads, 1 query per thread
__global__ __launch_bounds__(256, 1) void attn_k(const float* __restrict__ Qp,
                                                 const float* __restrict__ Kp,
                                                 const float* __restrict__ Vp,
                                                 float* __restrict__ Msg) {
    __shared__ __align__(16) float4 ksh[64 * 16];
    __shared__ __align__(16) float4 vsh[64 * 16];
    int h = blockIdx.y;
    int n = blockIdx.x * 256 + threadIdx.x;

    // q packed: q2[p] = {q[2p], q[2p+1]} * 1/sqrt(64)
    ull q2[32];
    {
        const float4* qrow = (const float4*)(Qp + ((size_t)h * AN + n) * AD);
#pragma unroll
        for (int i = 0; i < 16; i++) {
            float4 t = qrow[i];
            q2[2 * i + 0] = pack2(t.x * 0.125f, t.y * 0.125f);
            q2[2 * i + 1] = pack2(t.z * 0.125f, t.w * 0.125f);
        }
    }
    ull O2[32];
#pragma unroll
    for (int i = 0; i < 32; i++) O2[i] = 0ull;
    float mx = -1e30f, l = 0.f;

    for (int m0 = 0; m0 < AN; m0 += 64) {
        const float4* Ks = (const float4*)(Kp + ((size_t)h * AN + m0) * AD);
        const float4* Vs = (const float4*)(Vp + ((size_t)h * AN + m0) * AD);
        __syncthreads();
#pragma unroll
        for (int i = 0; i < 4; i++) {
            int idx = threadIdx.x + i * 256;
            ksh[idx] = Ks[idx];
            vsh[idx] = Vs[idx];
        }
        __syncthreads();
#pragma unroll 2
        for (int j = 0; j < 64; j++) {
            const ulonglong2* kr = (const ulonglong2*)&ksh[j * 16];
            ull a0 = 0ull, a1 = 0ull, a2 = 0ull, a3 = 0ull;
#pragma unroll
            for (int i = 0; i < 16; i += 2) {
                ulonglong2 t0 = kr[i], t1 = kr[i + 1];
                a0 = fma2(q2[2 * i + 0], t0.x, a0);
                a1 = fma2(q2[2 * i + 1], t0.y, a1);
                a2 = fma2(q2[2 * i + 2], t1.x, a2);
                a3 = fma2(q2[2 * i + 3], t1.y, a3);
            }
            ull s2 = add2(add2(a0, a1), add2(a2, a3));
            float slo, shi;
            unpack2(s2, slo, shi);
            float s = slo + shi;

            float p;
            if (s > mx) {
                float sc = __expf(mx - s);
                l *= sc;
                mx = s;
                p = 1.f;
                ull sc2 = pack2(sc, sc);
#pragma unroll
                for (int i = 0; i < 32; i++) O2[i] = mul2(O2[i], sc2);
            } else {
                p = __expf(s - mx);
            }
            l += p;
            ull pv = pack2(p, p);
            const ulonglong2* vr = (const ulonglong2*)&vsh[j * 16];
#pragma unroll
            for (int i = 0; i < 16; i++) {
                ulonglong2 t = vr[i];
                O2[2 * i + 0] = fma2(pv, t.x, O2[2 * i + 0]);
                O2[2 * i + 1] = fma2(pv, t.y, O2[2 * i + 1]);
            }
        }
    }
    float inv = 1.f / l;
    // Msg[(d*4+h)*AN + n] ; base offset h*AN + n, stride per d is 4*AN
    float* base = Msg + (size_t)h * AN + n;
#pragma unroll
    for (int i = 0; i < 32; i++) {
        float x0, x1;
        unpack2(O2[i], x0, x1);
        base[(size_t)(4 * (2 * i + 0)) * AN] = x0 * inv;
        base[(size_t)(4 * (2 * i + 1)) * AN] = x1 * inv;
    }
}

// ---------------- InstanceNorm (biased var) + ReLU, in place, per channel ----------------
__global__ __launch_bounds__(256) void inorm_relu(float* __restrict__ Y) {
    const int Nn = AN;
    float* row = Y + (size_t)blockIdx.x * Nn;
    __shared__ float red[256];
    int tid = threadIdx.x;

    float s = 0.f;
    for (int i = tid; i < Nn; i += 256) s += row[i];
    red[tid] = s;
    __syncthreads();
    for (int off = 128; off > 0; off >>= 1) {
        if (tid < off) red[tid] += red[tid + off];
        __syncthreads();
    }
    float mean = red[0] * (1.f / Nn);
    __syncthreads();

    float ss = 0.f;
    for (int i = tid; i < Nn; i += 256) {
        float d = row[i] - mean;
        ss += d * d;
    }
    red[tid] = ss;
    __syncthreads();
    for (int off = 128; off > 0; off >>= 1) {
        if (tid < off) red[tid] += red[tid + off];
        __syncthreads();
    }
    float rstd = rsqrtf(red[0] * (1.f / Nn) + 1e-5f);

    for (int i = tid; i < Nn; i += 256) {
        float v = (row[i] - mean) * rstd;
        row[i] = v > 0.f ? v : 0.f;
    }
}

// ---------------- launch ----------------
extern "C" void kernel_launch(void* const* d_in, const int* in_sizes, int n_in,
                              void* d_out, int out_size) {
    const float* descs = (const float*)d_in[0];
    const float* Wq = (const float*)d_in[1];
    const float* bq = (const float*)d_in[2];
    const float* Wk = (const float*)d_in[3];
    const float* bk = (const float*)d_in[4];
    const float* Wv = (const float*)d_in[5];
    const float* bv = (const float*)d_in[6];
    const float* Wm = (const float*)d_in[7];
    const float* bm = (const float*)d_in[8];
    const float* W1 = (const float*)d_in[9];
    const float* b1 = (const float*)d_in[10];
    const float* W2 = (const float*)d_in[11];
    const float* b2 = (const float*)d_in[12];
    float* out = (float*)d_out;

    float *xm, *q, *k, *v, *msg, *y, *z;
    cudaGetSymbolAddress((void**)&xm, g_XM);
    cudaGetSymbolAddress((void**)&q, g_Q);
    cudaGetSymbolAddress((void**)&k, g_K);
    cudaGetSymbolAddress((void**)&v, g_V);
    cudaGetSymbolAddress((void**)&msg, g_Msg);
    cudaGetSymbolAddress((void**)&y, g_Y);
    cudaGetSymbolAddress((void**)&z, g_Z);

    dim3 tb(32, 8);

    // 1) X = descs^T into g_XM rows [0,256)
    transpose_in<<<dim3(AN / 32, AC / 32), tb>>>(descs, xm);

    // 2) Q/K/V projections, written directly in [h][n][d]
    gemm_k<1><<<dim3(AN / 64, AC / 64), 256>>>(Wq, xm, bq, q, AC, AN, AC);
    gemm_k<1><<<dim3(AN / 64, AC / 64), 256>>>(Wk, xm, bk, k, AC, AN, AC);
    gemm_k<1><<<dim3(AN / 64, AC / 64), 256>>>(Wv, xm, bv, v, AC, AN, AC);

    // 3) attention -> g_Msg [c][n]
    attn_k<<<dim3(AN / 256, AH), 256>>>(q, k, v, msg);

    // 4) Wm @ msg + bm -> g_XM rows [256,512)  (forms concat(x, msg2))
    gemm_k<0><<<dim3(AN / 64, AC / 64), 256>>>(Wm, msg, bm, xm + (size_t)AC * AN, AC, AN, AC);

    // 5) Y = W1 @ concat + b1
    gemm_k<0><<<dim3(AN / 64, AC2 / 64), 256>>>(W1, xm, b1, y, AC2, AN, AC2);

    // 6) InstanceNorm + ReLU in place
    inorm_relu<<<AC2, 256>>>(y);

    // 7) Z = W2 @ Yn + b2
    gemm_k<0><<<dim3(AN / 64, AC / 64), 256>>>(W2, y, b2, z, AC, AN, AC2);

    // 8) out = descs + Z^T
    transpose_add<<<dim3(AN / 32, AC / 32), tb>>>(descs, z, out);
}

// round 3
// speedup vs baseline: 1.1698x; 1.0981x over previous
#include <cuda_runtime.h>
#include <cstddef>

#define AN 8192          // sequence length
#define AC 256           // channels
#define AH 4             // heads
#define AD 64            // head dim
#define AC2 512          // 2*C

typedef unsigned long long ull;

// ---------------- packed f32x2 helpers ----------------
__device__ __forceinline__ ull fma2(ull a, ull b, ull c) {
    ull d;
    asm("fma.rn.f32x2 %0, %1, %2, %3;" : "=l"(d) : "l"(a), "l"(b), "l"(c));
    return d;
}
__device__ __forceinline__ ull mul2(ull a, ull b) {
    ull d;
    asm("mul.rn.f32x2 %0, %1, %2;" : "=l"(d) : "l"(a), "l"(b));
    return d;
}
__device__ __forceinline__ ull pack2(float x, float y) {
    ull r;
    asm("mov.b64 %0, {%1, %2};" : "=l"(r) : "f"(x), "f"(y));
    return r;
}
__device__ __forceinline__ void unpack2(ull v, float& x, float& y) {
    asm("mov.b64 {%0, %1}, %2;" : "=f"(x), "=f"(y) : "l"(v));
}
__device__ __forceinline__ float ex2(float x) {
    float y;
    asm("ex2.approx.f32 %0, %1;" : "=f"(y) : "f"(x));
    return y;
}
__device__ __forceinline__ unsigned smem_u32(const void* p) {
    unsigned r;
    asm("{.reg .u64 t; cvta.to.shared.u64 t, %1; cvt.u32.u64 %0, t;}" : "=r"(r) : "l"(p));
    return r;
}
#define CPASYNC16(dst, src) \
    asm volatile("cp.async.cg.shared.global [%0], [%1], 16;" :: "r"(dst), "l"(src))
#define CPASYNC_COMMIT() asm volatile("cp.async.commit_group;" ::: "memory")
#define CPASYNC_WAIT0()  asm volatile("cp.async.wait_group 0;" ::: "memory")

// ---------------- scratch (allocation-free, device globals) ----------------
__device__ float g_XM[(size_t)AC2 * AN];      // rows 0..255: X = descs^T ; rows 256..511: Wm@msg
__device__ float g_Q[(size_t)AH * AN * AD];   // [h][n][d]
__device__ float g_K[(size_t)AH * AN * AD];
__device__ float g_V[(size_t)AH * AN * AD];
__device__ float g_Msg[(size_t)AC * AN];      // attention output, channel-major [c][n]
__device__ float g_Y[(size_t)AC2 * AN];       // after W1 (then normed in place)
__device__ float g_Z[(size_t)AC * AN];        // after W2

// ---------------- transpose: X[c][n] = descs[n][c] ----------------
__global__ __launch_bounds__(256) void transpose_in(const float* __restrict__ descs,
                                                    float* __restrict__ X) {
    __shared__ float tile[32][33];
    int n0 = blockIdx.x * 32, c0 = blockIdx.y * 32;
    int tx = threadIdx.x, ty = threadIdx.y;
#pragma unroll
    for (int r = 0; r < 4; r++) {
        int n = n0 + ty + r * 8;
        tile[ty + r * 8][tx] = descs[(size_t)n * AC + c0 + tx];
    }
    __syncthreads();
#pragma unroll
    for (int r = 0; r < 4; r++) {
        int c = c0 + ty + r * 8;
        X[(size_t)c * AN + n0 + tx] = tile[tx][ty + r * 8];
    }
}

// ---------------- out[n][c] = descs[n][c] + Z[c][n] ----------------
__global__ __launch_bounds__(256) void transpose_add(const float* __restrict__ descs,
                                                     const float* __restrict__ Z,
                                                     float* __restrict__ out) {
    __shared__ float tile[32][33];
    int n0 = blockIdx.x * 32, c0 = blockIdx.y * 32;
    int tx = threadIdx.x, ty = threadIdx.y;
#pragma unroll
    for (int r = 0; r < 4; r++) {
        int c = c0 + ty + r * 8;
        tile[ty + r * 8][tx] = Z[(size_t)c * AN + n0 + tx];
    }
    __syncthreads();
#pragma unroll
    for (int r = 0; r < 4; r++) {
        int n = n0 + ty + r * 8;
        size_t idx = (size_t)n * AC + c0 + tx;
        out[idx] = descs[idx] + tile[tx][ty + r * 8];
    }
}

// ---------------- fp32 GEMM: C = A[M,K] @ B[K,N] + bias ----------------
template <int OUTMODE>
__global__ __launch_bounds__(256) void gemm_k(const float* __restrict__ A,
                                              const float* __restrict__ B,
                                              const float* __restrict__ bias,
                                              float* __restrict__ C,
                                              int M, int Nn, int K) {
    __shared__ __align__(16) float As[2][16][64];   // As[buf][k][m]
    __shared__ __align__(16) float Bs[2][16][64];   // Bs[buf][k][n]
    int tid = threadIdx.x;
    int n0 = blockIdx.x * 64;
    int m0 = blockIdx.y * 64;
    int tx = tid & 15, ty = tid >> 4;
    int ar = tid >> 2, ac4 = tid & 3;
    int br = tid >> 4, bc4 = tid & 15;

    ull acc2[4][2];
#pragma unroll
    for (int i = 0; i < 4; i++) { acc2[i][0] = 0ull; acc2[i][1] = 0ull; }

    {
        float4 a = *(const float4*)&A[(size_t)(m0 + ar) * K + ac4 * 4];
        float4 b = *(const float4*)&B[(size_t)br * Nn + n0 + bc4 * 4];
        As[0][ac4 * 4 + 0][ar] = a.x;
        As[0][ac4 * 4 + 1][ar] = a.y;
        As[0][ac4 * 4 + 2][ar] = a.z;
        As[0][ac4 * 4 + 3][ar] = a.w;
        *(float4*)&Bs[0][br][bc4 * 4] = b;
    }
    __syncthreads();

    int nIter = K >> 4;
    for (int it = 0; it < nIter; it++) {
        int cur = it & 1;
        float4 an, bn;
        bool has_next = (it + 1 < nIter);
        if (has_next) {
            int k0 = (it + 1) << 4;
            an = *(const float4*)&A[(size_t)(m0 + ar) * K + k0 + ac4 * 4];
            bn = *(const float4*)&B[(size_t)(k0 + br) * Nn + n0 + bc4 * 4];
        }
#pragma unroll
        for (int kk = 0; kk < 16; kk++) {
            float4 av = *(const float4*)&As[cur][kk][ty * 4];
            ulonglong2 bb = *(const ulonglong2*)&Bs[cur][kk][tx * 4];
            ull a0 = pack2(av.x, av.x);
            ull a1 = pack2(av.y, av.y);
            ull a2 = pack2(av.z, av.z);
            ull a3 = pack2(av.w, av.w);
            acc2[0][0] = fma2(a0, bb.x, acc2[0][0]);
            acc2[0][1] = fma2(a0, bb.y, acc2[0][1]);
            acc2[1][0] = fma2(a1, bb.x, acc2[1][0]);
            acc2[1][1] = fma2(a1, bb.y, acc2[1][1]);
            acc2[2][0] = fma2(a2, bb.x, acc2[2][0]);
            acc2[2][1] = fma2(a2, bb.y, acc2[2][1]);
            acc2[3][0] = fma2(a3, bb.x, acc2[3][0]);
            acc2[3][1] = fma2(a3, bb.y, acc2[3][1]);
        }
        if (has_next) {
            int nxt = cur ^ 1;
            As[nxt][ac4 * 4 + 0][ar] = an.x;
            As[nxt][ac4 * 4 + 1][ar] = an.y;
            As[nxt][ac4 * 4 + 2][ar] = an.z;
            As[nxt][ac4 * 4 + 3][ar] = an.w;
            *(float4*)&Bs[nxt][br][bc4 * 4] = bn;
            __syncthreads();
        }
    }

#pragma unroll
    for (int i = 0; i < 4; i++) {
        int m = m0 + ty * 4 + i;
        float bv = bias[m];
        float c0, c1, c2, c3;
        unpack2(acc2[i][0], c0, c1);
        unpack2(acc2[i][1], c2, c3);
        float vals[4] = {c0 + bv, c1 + bv, c2 + bv, c3 + bv};
#pragma unroll
        for (int j = 0; j < 4; j++) {
            int n = n0 + tx * 4 + j;
            if (OUTMODE == 0) {
                C[(size_t)m * Nn + n] = vals[j];
            } else {
                C[(size_t)(m & 3) * ((size_t)Nn * AD) + (size_t)n * AD + (m >> 2)] = vals[j];
            }
        }
    }
}

// ---------------- flash attention: 16-key batched softmax, cp.async pipeline ----------------
// grid: (AN/256, AH), 256 threads, 1 query per thread; 32 keys staged per iteration.
__global__ __launch_bounds__(256, 1) void attn_k(const float* __restrict__ Qp,
                                                 const float* __restrict__ Kp,
                                                 const float* __restrict__ Vp,
                                                 float* __restrict__ Msg) {
    __shared__ __align__(16) float4 ksh[2][32 * 16];
    __shared__ __align__(16) float4 vsh[2][32 * 16];
    int h = blockIdx.y;
    int tid = threadIdx.x;
    int n = blockIdx.x * 256 + tid;

    const float* Kbase = Kp + (size_t)h * AN * AD;
    const float* Vbase = Vp + (size_t)h * AN * AD;

    // q packed, pre-scaled by 1/sqrt(64) * log2(e)  -> softmax in exp2 domain
    ull q2[32];
    {
        const float4* qrow = (const float4*)(Qp + ((size_t)h * AN + n) * AD);
        const float qs = 0.125f * 1.4426950408889634f;
#pragma unroll
        for (int i = 0; i < 16; i++) {
            float4 t = qrow[i];
            q2[2 * i + 0] = pack2(t.x * qs, t.y * qs);
            q2[2 * i + 1] = pack2(t.z * qs, t.w * qs);
        }
    }
    ull O2[32];
#pragma unroll
    for (int i = 0; i < 32; i++) O2[i] = 0ull;
    float mx = -1e30f, l = 0.f;

    unsigned kd0 = smem_u32(&ksh[0][0]);
    unsigned vd0 = smem_u32(&vsh[0][0]);
    const unsigned BUFB = 32 * 16 * 16;  // bytes per buffer

    // prologue: stage 0
    {
        const float4* Ks = (const float4*)Kbase;
        const float4* Vs = (const float4*)Vbase;
        CPASYNC16(kd0 + tid * 16u, Ks + tid);
        CPASYNC16(kd0 + (tid + 256) * 16u, Ks + tid + 256);
        CPASYNC16(vd0 + tid * 16u, Vs + tid);
        CPASYNC16(vd0 + (tid + 256) * 16u, Vs + tid + 256);
        CPASYNC_COMMIT();
        CPASYNC_WAIT0();
    }
    __syncthreads();

    const int nBlk = AN / 32;
    for (int it = 0; it < nBlk; it++) {
        int cur = it & 1;
        bool has_next = (it + 1 < nBlk);
        if (has_next) {
            int m0 = (it + 1) * 32;
            const float4* Ks = (const float4*)(Kbase + (size_t)m0 * AD);
            const float4* Vs = (const float4*)(Vbase + (size_t)m0 * AD);
            unsigned kd = kd0 + (cur ^ 1) * BUFB;
            unsigned vd = vd0 + (cur ^ 1) * BUFB;
            CPASYNC16(kd + tid * 16u, Ks + tid);
            CPASYNC16(kd + (tid + 256) * 16u, Ks + tid + 256);
            CPASYNC16(vd + tid * 16u, Vs + tid);
            CPASYNC16(vd + (tid + 256) * 16u, Vs + tid + 256);
            CPASYNC_COMMIT();
        }

#pragma unroll
        for (int jb = 0; jb < 32; jb += 16) {
            // --- phase 1: 16 scores (independent chains) ---
            float s[16];
#pragma unroll
            for (int j = 0; j < 16; j++) {
                const ulonglong2* kr = (const ulonglong2*)&ksh[cur][(jb + j) * 16];
                ull a0 = 0ull, a1 = 0ull;
#pragma unroll
                for (int i = 0; i < 16; i++) {
                    ulonglong2 t = kr[i];
                    a0 = fma2(q2[2 * i + 0], t.x, a0);
                    a1 = fma2(q2[2 * i + 1], t.y, a1);
                }
                float x0, x1, y0, y1;
                unpack2(a0, x0, x1);
                unpack2(a1, y0, y1);
                s[j] = (x0 + x1) + (y0 + y1);
            }
            // --- phase 2: block max, one rescale per 16 keys ---
            float bm = fmaxf(s[0], s[1]);
#pragma unroll
            for (int j = 2; j < 16; j++) bm = fmaxf(bm, s[j]);
            if (bm > mx) {
                float sc = ex2(mx - bm);
                mx = bm;
                l *= sc;
                ull sc2 = pack2(sc, sc);
#pragma unroll
                for (int i = 0; i < 32; i++) O2[i] = mul2(O2[i], sc2);
            }
            // --- phase 3: probabilities ---
            float p[16];
#pragma unroll
            for (int j = 0; j < 16; j++) p[j] = ex2(s[j] - mx);
            float ls = 0.f;
#pragma unroll
            for (int j = 0; j < 16; j += 4)
                ls += ((p[j] + p[j + 1]) + (p[j + 2] + p[j + 3]));
            l += ls;
            // --- phase 4: PV accumulate (branch-free) ---
#pragma unroll
            for (int j = 0; j < 16; j++) {
                ull pv = pack2(p[j], p[j]);
                const ulonglong2* vr = (const ulonglong2*)&vsh[cur][(jb + j) * 16];
#pragma unroll
                for (int i = 0; i < 16; i++) {
                    ulonglong2 t = vr[i];
                    O2[2 * i + 0] = fma2(pv, t.x, O2[2 * i + 0]);
                    O2[2 * i + 1] = fma2(pv, t.y, O2[2 * i + 1]);
                }
            }
        }

        if (has_next) {
            CPASYNC_WAIT0();
            __syncthreads();
        }
    }

    float inv = 1.f / l;
    // Msg[(d*4+h)*AN + n]
    float* base = Msg + (size_t)h * AN + n;
#pragma unroll
    for (int i = 0; i < 32; i++) {
        float x0, x1;
        unpack2(O2[i], x0, x1);
        base[(size_t)(4 * (2 * i + 0)) * AN] = x0 * inv;
        base[(size_t)(4 * (2 * i + 1)) * AN] = x1 * inv;
    }
}

// ---------------- InstanceNorm (biased var) + ReLU, in place, per channel ----------------
__global__ __launch_bounds__(256) void inorm_relu(float* __restrict__ Y) {
    const int Nn = AN;
    float* row = Y + (size_t)blockIdx.x * Nn;
    __shared__ float red[256];
    int tid = threadIdx.x;

    float s = 0.f;
    for (int i = tid; i < Nn; i += 256) s += row[i];
    red[tid] = s;
    __syncthreads();
    for (int off = 128; off > 0; off >>= 1) {
        if (tid < off) red[tid] += red[tid + off];
        __syncthreads();
    }
    float mean = red[0] * (1.f / Nn);
    __syncthreads();

    float ss = 0.f;
    for (int i = tid; i < Nn; i += 256) {
        float d = row[i] - mean;
        ss += d * d;
    }
    red[tid] = ss;
    __syncthreads();
    for (int off = 128; off > 0; off >>= 1) {
        if (tid < off) red[tid] += red[tid + off];
        __syncthreads();
    }
    float rstd = rsqrtf(red[0] * (1.f / Nn) + 1e-5f);

    for (int i = tid; i < Nn; i += 256) {
        float v = (row[i] - mean) * rstd;
        row[i] = v > 0.f ? v : 0.f;
    }
}

// ---------------- launch ----------------
extern "C" void kernel_launch(void* const* d_in, const int* in_sizes, int n_in,
                              void* d_out, int out_size) {
    const float* descs = (const float*)d_in[0];
    const float* Wq = (const float*)d_in[1];
    const float* bq = (const float*)d_in[2];
    const float* Wk = (const float*)d_in[3];
    const float* bk = (const float*)d_in[4];
    const float* Wv = (const float*)d_in[5];
    const float* bv = (const float*)d_in[6];
    const float* Wm = (const float*)d_in[7];
    const float* bm = (const float*)d_in[8];
    const float* W1 = (const float*)d_in[9];
    const float* b1 = (const float*)d_in[10];
    const float* W2 = (const float*)d_in[11];
    const float* b2 = (const float*)d_in[12];
    float* out = (float*)d_out;

    float *xm, *q, *k, *v, *msg, *y, *z;
    cudaGetSymbolAddress((void**)&xm, g_XM);
    cudaGetSymbolAddress((void**)&q, g_Q);
    cudaGetSymbolAddress((void**)&k, g_K);
    cudaGetSymbolAddress((void**)&v, g_V);
    cudaGetSymbolAddress((void**)&msg, g_Msg);
    cudaGetSymbolAddress((void**)&y, g_Y);
    cudaGetSymbolAddress((void**)&z, g_Z);

    dim3 tb(32, 8);

    transpose_in<<<dim3(AN / 32, AC / 32), tb>>>(descs, xm);

    gemm_k<1><<<dim3(AN / 64, AC / 64), 256>>>(Wq, xm, bq, q, AC, AN, AC);
    gemm_k<1><<<dim3(AN / 64, AC / 64), 256>>>(Wk, xm, bk, k, AC, AN, AC);
    gemm_k<1><<<dim3(AN / 64, AC / 64), 256>>>(Wv, xm, bv, v, AC, AN, AC);

    attn_k<<<dim3(AN / 256, AH), 256>>>(q, k, v, msg);

    gemm_k<0><<<dim3(AN / 64, AC / 64), 256>>>(Wm, msg, bm, xm + (size_t)AC * AN, AC, AN, AC);

    gemm_k<0><<<dim3(AN / 64, AC2 / 64), 256>>>(W1, xm, b1, y, AC2, AN, AC2);

    inorm_relu<<<AC2, 256>>>(y);

    gemm_k<0><<<dim3(AN / 64, AC / 64), 256>>>(W2, y, b2, z, AC, AN, AC2);

    transpose_add<<<dim3(AN / 32, AC / 32), tb>>>(descs, z, out);
}